// round 11
// baseline (speedup 1.0000x reference)
#include <cuda_runtime.h>
#include <cstdint>

#define NB 32
#define LQ 18
#define LK 4096
#define DD 768
#define SCALE_F 0.03608439182435161f   // 1/sqrt(768)

// ---- p1 config ----
#define T1   256
#define MT   128             // k-rows per p1 block
#define NMT  (LK/MT)         // 32
#define NP1  (NB*NMT)        // 1024 p1 blocks
#define CC   16              // K cols per chunk
#define NCH  (DD/CC)         // 48
#define QSTR 1544            // Q row stride bytes (768*2 + 8 pad)
#define WSTG 4096            // per-warp staging: 4 bufs x 1024B

// ---- p2 config ----
#define TK2 256
#define NT2 (LK/TK2)         // 16
#define NP2 (NB*NT2)         // 512 p2 blocks

// smem layout (bytes)
#define SM_U8   0
#define SM_LAST 8
#define SM_WL   64           // p2: 18 floats (alias; p1 uses SM_RED here too - distinct blocks)
#define SM_RED  192          // p1: 8 warps * 24 floats = 768B -> ends 960
#define SM_SA   1024         // p2: 256 floats = 1024B (aliases SM_QHI; p2 blocks don't use Q)
#define SM_QHI  1024         // 27792
#define SM_QLO  28816        // 27792 -> ends 56608
#define SM_STG  56640        // 8 warps * 4096
#define SMEM_BYTES (SM_STG + 8*WSTG)   // 89408

// ---- device scratch (zero-init, self-cleaning) ----
__device__ float g_e[(size_t)NB*LQ*LK];
__device__ float g_lp[NB][NMT][LQ];
__device__ float g_cp[NB][NT2][DD];
__device__ int   g_cntA[NB];
__device__ int   g_cntB[NB];

__device__ __forceinline__ uint32_t bfpack(float a, float b) {   // low16=bf16(a)
    uint32_t r;
    asm("cvt.rn.bf16x2.f32 %0, %1, %2;" : "=r"(r) : "f"(b), "f"(a));
    return r;
}
__device__ __forceinline__ float bflo_f(uint32_t h) { return __uint_as_float(h << 16); }
__device__ __forceinline__ float bfhi_f(uint32_t h) { return __uint_as_float(h & 0xffff0000u); }
__device__ __forceinline__ uint32_t smem_u32(const void* p) {
    uint32_t a;
    asm("{ .reg .u64 t; cvta.to.shared.u64 t, %1; cvt.u32.u64 %0, t; }" : "=r"(a) : "l"(p));
    return a;
}
#define CP_ASYNC16(dst, src) \
    asm volatile("cp.async.cg.shared.global [%0], [%1], 16;" :: "r"(dst), "l"(src) : "memory")
#define CP_COMMIT() asm volatile("cp.async.commit_group;" ::: "memory")
#define CP_WAITN(n) asm volatile("cp.async.wait_group %0;" :: "n"(n) : "memory")
#define MMA(ac, a0,a1,a2,a3, b0,b1) \
    asm volatile("mma.sync.aligned.m16n8k16.row.col.f32.bf16.bf16.f32 " \
        "{%0,%1,%2,%3}, {%4,%5,%6,%7}, {%8,%9}, {%0,%1,%2,%3};" \
        : "+f"((ac)[0]),"+f"((ac)[1]),"+f"((ac)[2]),"+f"((ac)[3]) \
        : "r"(a0),"r"(a1),"r"(a2),"r"(a3),"r"(b0),"r"(b1))

__device__ __forceinline__ void bfsplit(float2 v, uint32_t& h, uint32_t& l) {
    h = bfpack(v.x, v.y);
    l = bfpack(v.x - bflo_f(h), v.y - bfhi_f(h));
}

__global__ __launch_bounds__(T1, 2) void fused(const float* __restrict__ Q,
                                               const float* __restrict__ K,
                                               const float* __restrict__ V,
                                               const void* __restrict__ Mv,
                                               const float* __restrict__ W,
                                               float* __restrict__ out) {
    extern __shared__ char smem[];
    const uint32_t sb = smem_u32(smem);
    const int tid = threadIdx.x, w = tid >> 5, lane = tid & 31;
    const int bid = blockIdx.x;

    if (bid < NP1) {
        // ================= p1 block: scores^T tile (R10 body) =================
        const int gid = lane >> 2, tig = lane & 3;
        const int b = bid >> 5, mt = bid & 31, k0 = mt * MT;
        const int M0 = w * 16;

        if (tid == 0) *(int*)(smem + SM_U8) = 0;
        __syncthreads();
        // mask dtype probe: int32 0/1 has zero bytes at offsets %4!=0; u8 bool does not
        if (tid < 64) {
            uchar4 v = ((const uchar4*)Mv)[tid];
            if (v.y | v.z | v.w) atomicOr((int*)(smem + SM_U8), 1);
        }

        const uint32_t stg = sb + SM_STG + w * WSTG;
        const float* Kw = K + ((size_t)b * LK + k0 + M0) * DD;

#pragma unroll
        for (int cc = 0; cc < 3; cc++) {
            const uint32_t dst = stg + (cc & 3) * 1024;
            const float* src = Kw + cc * CC;
#pragma unroll
            for (int i = 0; i < 2; i++) {
                int g = i * 32 + lane, r = g >> 2, f = g & 3;
                CP_ASYNC16(dst + (uint32_t)(r * 4 + (f ^ (r & 3))) * 16,
                           src + (size_t)r * DD + f * 4);
            }
            CP_COMMIT();
        }

        {   // Q -> bf16 hi/lo smem (once per block)
            const float4* Q4 = (const float4*)(Q + (size_t)b * LQ * DD);
            for (int idx = tid; idx < LQ * 192; idx += T1) {
                int q = idx / 192, f = idx % 192;
                float4 v = Q4[idx];
                uint32_t h0 = bfpack(v.x, v.y), h1 = bfpack(v.z, v.w);
                uint32_t l0 = bfpack(v.x - bflo_f(h0), v.y - bfhi_f(h0));
                uint32_t l1 = bfpack(v.z - bflo_f(h1), v.w - bfhi_f(h1));
                *(uint2*)(smem + SM_QHI + q * QSTR + f * 8) = make_uint2(h0, h1);
                *(uint2*)(smem + SM_QLO + q * QSTR + f * 8) = make_uint2(l0, l1);
            }
        }
        __syncthreads();

        float acc[3][4];
#pragma unroll
        for (int nt = 0; nt < 3; nt++)
#pragma unroll
            for (int i = 0; i < 4; i++) acc[nt][i] = 0.f;

        const int fA = tig >> 1, hA = tig & 1;
        const uint32_t oa0 = (uint32_t)((gid * 4 + (fA ^ (gid & 3))) * 16 + hA * 8);
        const uint32_t oa1 = (uint32_t)(((gid + 8) * 4 + (fA ^ ((gid + 8) & 3))) * 16 + hA * 8);
        const uint32_t oa2 = (uint32_t)((gid * 4 + ((fA + 2) ^ (gid & 3))) * 16 + hA * 8);
        const uint32_t oa3 = (uint32_t)(((gid + 8) * 4 + ((fA + 2) ^ ((gid + 8) & 3))) * 16 + hA * 8);

        for (int c = 0; c < NCH; c++) {
            if (c + 3 < NCH) {
                const uint32_t dst = stg + ((c + 3) & 3) * 1024;
                const float* src = Kw + (c + 3) * CC;
#pragma unroll
                for (int i = 0; i < 2; i++) {
                    int g = i * 32 + lane, r = g >> 2, f = g & 3;
                    CP_ASYNC16(dst + (uint32_t)(r * 4 + (f ^ (r & 3))) * 16,
                               src + (size_t)r * DD + f * 4);
                }
                CP_COMMIT();
                CP_WAITN(3);
            } else {
                int rem = NCH - 1 - c;
                if (rem == 2)      CP_WAITN(2);
                else if (rem == 1) CP_WAITN(1);
                else               CP_WAITN(0);
            }

            const char* buf = smem + (stg - sb) + (c & 3) * 1024;
            uint32_t ah0, ah1, ah2, ah3, al0, al1, al2, al3;
            bfsplit(*(const float2*)(buf + oa0), ah0, al0);
            bfsplit(*(const float2*)(buf + oa1), ah1, al1);
            bfsplit(*(const float2*)(buf + oa2), ah2, al2);
            bfsplit(*(const float2*)(buf + oa3), ah3, al3);

            const int dglob = c * CC + tig * 2;
#pragma unroll
            for (int nt = 0; nt < 3; nt++) {
                int q = nt * 8 + gid; if (q > 17) q = 17;
                const char* qh = smem + SM_QHI + q * QSTR + dglob * 2;
                const char* ql = smem + SM_QLO + q * QSTR + dglob * 2;
                uint32_t bh0 = *(const uint32_t*)qh;
                uint32_t bh1 = *(const uint32_t*)(qh + 16);
                uint32_t bl0 = *(const uint32_t*)ql;
                uint32_t bl1 = *(const uint32_t*)(ql + 16);
                MMA(acc[nt], ah0, ah1, ah2, ah3, bh0, bh1);
                MMA(acc[nt], ah0, ah1, ah2, ah3, bl0, bl1);
                MMA(acc[nt], al0, al1, al2, al3, bh0, bh1);
            }
        }

        // epilogue: mask + exp + g_e + per-q row sums
        const int u8 = *(volatile int*)(smem + SM_U8);
        const unsigned char* M8  = (const unsigned char*)Mv;
        const int*           M32 = (const int*)Mv;
        float* red = (float*)(smem + SM_RED);
        const int ra = M0 + gid, rb = ra + 8;
#pragma unroll
        for (int nt = 0; nt < 3; nt++) {
            const int q0 = nt * 8 + tig * 2, q1 = q0 + 1;
            float e0 = 0.f, e1 = 0.f, e2 = 0.f, e3 = 0.f;
            if (q0 < LQ) {
                size_t o = ((size_t)b * LQ + q0) * LK + k0;
                int m0 = u8 ? (int)M8[o + ra] : M32[o + ra];
                int m2 = u8 ? (int)M8[o + rb] : M32[o + rb];
                e0 = m0 ? 0.f : __expf(acc[nt][0] * SCALE_F);
                e2 = m2 ? 0.f : __expf(acc[nt][2] * SCALE_F);
                g_e[o + ra] = e0;
                g_e[o + rb] = e2;
            }
            if (q1 < LQ) {
                size_t o = ((size_t)b * LQ + q1) * LK + k0;
                int m1 = u8 ? (int)M8[o + ra] : M32[o + ra];
                int m3 = u8 ? (int)M8[o + rb] : M32[o + rb];
                e1 = m1 ? 0.f : __expf(acc[nt][1] * SCALE_F);
                e3 = m3 ? 0.f : __expf(acc[nt][3] * SCALE_F);
                g_e[o + ra] = e1;
                g_e[o + rb] = e3;
            }
            float s0 = e0 + e2, s1 = e1 + e3;
#pragma unroll
            for (int m = 4; m <= 16; m <<= 1) {
                s0 += __shfl_xor_sync(0xffffffffu, s0, m);
                s1 += __shfl_xor_sync(0xffffffffu, s1, m);
            }
            if (gid == 0) {
                if (q0 < LQ) red[w * 24 + q0] = s0;
                if (q1 < LQ) red[w * 24 + q1] = s1;
            }
        }
        __syncthreads();
        if (tid < LQ) {
            float l = 0.f;
#pragma unroll
            for (int ww = 0; ww < 8; ww++) l += red[ww * 24 + tid];
            g_lp[b][mt][tid] = l;
        }
        __syncthreads();
        if (tid == 0) { __threadfence(); atomicAdd(&g_cntA[b], 1); }   // release gate
    } else {
        // ================= p2 block: attn_fc + context (gated on batch) =================
        const int bid2 = bid - NP1;
        const int b = bid2 >> 4, t = bid2 & 15;
        const int k0 = t * TK2;
        float* wl = (float*)(smem + SM_WL);
        float* sa = (float*)(smem + SM_SA);

        if (tid == 0) {                 // gate: all 32 score tiles of batch b done
            while (atomicAdd(&g_cntA[b], 0) < NMT) __nanosleep(256);
            __threadfence();
        }
        __syncthreads();

        if (tid < LQ) {
            float l = 0.f;
#pragma unroll
            for (int tt = 0; tt < NMT; tt++) l += g_lp[b][tt][tid];
            wl[tid] = W[tid] / l;
        }
        __syncthreads();

        {   // attn_fc: one k per thread (TK2 == T1)
            const int k = k0 + tid;
            float a = 0.f;
#pragma unroll
            for (int q = 0; q < LQ; q++)
                a = fmaf(g_e[((size_t)b * LQ + q) * LK + k], wl[q], a);
            out[(size_t)NB * DD + (size_t)b * LK + k] = a;
            sa[tid] = a;
        }
        __syncthreads();

        if (tid < DD / 4) {             // context partial
            const float4* V4 = (const float4*)(V + ((size_t)b * LK + k0) * DD);
            float cx = 0.f, cy = 0.f, cz = 0.f, cw = 0.f;
#pragma unroll 8
            for (int kk = 0; kk < TK2; kk++) {
                float  av = sa[kk];
                float4 v  = V4[(size_t)kk * (DD / 4) + tid];
                cx = fmaf(av, v.x, cx);
                cy = fmaf(av, v.y, cy);
                cz = fmaf(av, v.z, cz);
                cw = fmaf(av, v.w, cw);
            }
            ((float4*)g_cp[b][t])[tid] = make_float4(cx, cy, cz, cw);
        }
        __threadfence();
        __syncthreads();
        if (tid == 0)
            *(volatile int*)(smem + SM_LAST) = (atomicAdd(&g_cntB[b], 1) == NT2 - 1);
        __syncthreads();
        if (*(volatile int*)(smem + SM_LAST)) {
            if (tid < DD / 4) {         // fixed-order deterministic reduction
                float4 a = make_float4(0.f, 0.f, 0.f, 0.f);
#pragma unroll
                for (int tt = 0; tt < NT2; tt++) {
                    float4 v = ((const float4*)g_cp[b][tt])[tid];
                    a.x += v.x; a.y += v.y; a.z += v.z; a.w += v.w;
                }
                ((float4*)(out + (size_t)b * DD))[tid] = a;
            }
            if (tid == 0) { g_cntA[b] = 0; g_cntB[b] = 0; }   // self-clean for replay
        }
    }
}

extern "C" void kernel_launch(void* const* d_in, const int* in_sizes, int n_in,
                              void* d_out, int out_size) {
    const float* Q = (const float*)d_in[0];
    const float* K = (const float*)d_in[1];
    const float* V = (const float*)d_in[2];
    const void*  M = d_in[3];
    const float* W = (const float*)d_in[4];
    float* out = (float*)d_out;

    cudaFuncSetAttribute(fused, cudaFuncAttributeMaxDynamicSharedMemorySize, SMEM_BYTES);
    fused<<<NP1 + NP2, T1, SMEM_BYTES>>>(Q, K, V, M, W, out);
}

// round 12
// speedup vs baseline: 1.1170x; 1.1170x over previous
#include <cuda_runtime.h>
#include <cuda_fp16.h>
#include <cstdint>

#define NB 32
#define LQ 18
#define LK 4096
#define DD 768
#define SCALE_F 0.03608439182435161f   // 1/sqrt(768)

// ---- p1 config ----
#define T1   256
#define MT   256             // k-rows per p1 block (2 MMA row-blocks per warp)
#define NMT  (LK/MT)         // 16
#define CC   16              // K cols per chunk
#define NCH  (DD/CC)         // 48
#define QSTR 1544            // Q row stride bytes (768*2 + 8 pad)
#define WSTG 6144            // per-warp staging: 3 bufs x 2048B (32 rows x 64B)

// smem layout (bytes)
#define SM_U8   0
#define SM_RED  192          // 8 warps * 24 floats = 768B -> ends 960
#define SM_QHI  1024         // 27792
#define SM_QLO  28816        // 27792 -> ends 56608
#define SM_STG  56640        // 8 warps * 6144
#define SMEM1_BYTES (SM_STG + 8*WSTG)   // 105792

// scratch row: 24 halves (48B) per (b,k); q 18..23 = pad (never written, zero-init)
#define GH_STRIDE 24

// ---- p2 config ----
#define TK2 256
#define NT2 (LK/TK2)         // 16
#define T2  192

// ---- device scratch ----
__device__ __half g_h[(size_t)NB*LK*GH_STRIDE];   // exp(scores) fp16, transposed
__device__ float  g_lp[NB][NMT][LQ];
__device__ float  g_cp[NB][NT2][DD];
__device__ int    g_cnt[NB];

__device__ __forceinline__ uint32_t bfpack(float a, float b) {   // low16=bf16(a)
    uint32_t r;
    asm("cvt.rn.bf16x2.f32 %0, %1, %2;" : "=r"(r) : "f"(b), "f"(a));
    return r;
}
__device__ __forceinline__ float bflo_f(uint32_t h) { return __uint_as_float(h << 16); }
__device__ __forceinline__ float bfhi_f(uint32_t h) { return __uint_as_float(h & 0xffff0000u); }
__device__ __forceinline__ uint32_t smem_u32(const void* p) {
    uint32_t a;
    asm("{ .reg .u64 t; cvta.to.shared.u64 t, %1; cvt.u32.u64 %0, t; }" : "=r"(a) : "l"(p));
    return a;
}
#define CP_ASYNC16(dst, src) \
    asm volatile("cp.async.cg.shared.global [%0], [%1], 16;" :: "r"(dst), "l"(src) : "memory")
#define CP_COMMIT() asm volatile("cp.async.commit_group;" ::: "memory")
#define CP_WAITN(n) asm volatile("cp.async.wait_group %0;" :: "n"(n) : "memory")
#define MMA(ac, a0,a1,a2,a3, b0,b1) \
    asm volatile("mma.sync.aligned.m16n8k16.row.col.f32.bf16.bf16.f32 " \
        "{%0,%1,%2,%3}, {%4,%5,%6,%7}, {%8,%9}, {%0,%1,%2,%3};" \
        : "+f"((ac)[0]),"+f"((ac)[1]),"+f"((ac)[2]),"+f"((ac)[3]) \
        : "r"(a0),"r"(a1),"r"(a2),"r"(a3),"r"(b0),"r"(b1))

__device__ __forceinline__ void bfsplit(float2 v, uint32_t& h, uint32_t& l) {
    h = bfpack(v.x, v.y);
    l = bfpack(v.x - bflo_f(h), v.y - bfhi_f(h));
}

// ---------------- p1: 256-row tiles, register-fragment split-bf16 mma.sync ----------------
__global__ __launch_bounds__(T1, 2) void p1(const float* __restrict__ Q,
                                            const float* __restrict__ K,
                                            const void* __restrict__ Mv) {
    extern __shared__ char smem[];
    const uint32_t sb = smem_u32(smem);
    const int tid = threadIdx.x, w = tid >> 5, lane = tid & 31;
    const int gid = lane >> 2, tig = lane & 3;
    const int b = blockIdx.y, mt = blockIdx.x, k0 = mt * MT;
    const int M0 = w * 32;                 // warp owns 32 k-rows

    if (tid == 0) *(int*)(smem + SM_U8) = 0;
    __syncthreads();
    // mask dtype probe: int32 0/1 has zero bytes at offsets %4!=0; u8 bool does not
    if (tid < 64) {
        uchar4 v = ((const uchar4*)Mv)[tid];
        if (v.y | v.z | v.w) atomicOr((int*)(smem + SM_U8), 1);
    }

    // per-warp staging: chunk = 32 rows x 16 f32 (64B/row), xor-swizzled float4s
    const uint32_t stg = sb + SM_STG + w * WSTG;
    const float* Kw = K + ((size_t)b * LK + k0 + M0) * DD;

    // issue chunks 0,1 (depth-3 ring: bufs 0,1,2)
#pragma unroll
    for (int cc = 0; cc < 2; cc++) {
        const uint32_t dst = stg + cc * 2048;
        const float* src = Kw + cc * CC;
#pragma unroll
        for (int i = 0; i < 4; i++) {
            int g = i * 32 + lane, r = g >> 2, f = g & 3;
            CP_ASYNC16(dst + (uint32_t)(r * 4 + (f ^ (r & 3))) * 16,
                       src + (size_t)r * DD + f * 4);
        }
        CP_COMMIT();
    }

    {   // Q -> bf16 hi/lo smem (once per block)
        const float4* Q4 = (const float4*)(Q + (size_t)b * LQ * DD);
        for (int idx = tid; idx < LQ * 192; idx += T1) {
            int q = idx / 192, f = idx % 192;
            float4 v = Q4[idx];
            uint32_t h0 = bfpack(v.x, v.y), h1 = bfpack(v.z, v.w);
            uint32_t l0 = bfpack(v.x - bflo_f(h0), v.y - bfhi_f(h0));
            uint32_t l1 = bfpack(v.z - bflo_f(h1), v.w - bfhi_f(h1));
            *(uint2*)(smem + SM_QHI + q * QSTR + f * 8) = make_uint2(h0, h1);
            *(uint2*)(smem + SM_QLO + q * QSTR + f * 8) = make_uint2(l0, l1);
        }
    }
    __syncthreads();   // Q visible; main loop sync-free

    float acc[2][3][4];
#pragma unroll
    for (int rr = 0; rr < 2; rr++)
#pragma unroll
        for (int nt = 0; nt < 3; nt++)
#pragma unroll
            for (int i = 0; i < 4; i++) acc[rr][nt][i] = 0.f;

    // fragment offsets (local rows within warp's 32-row staging)
    const int fA = tig >> 1, hA = tig & 1;
#define STGOFF(r, f) ((uint32_t)(((r) * 4 + ((f) ^ ((r) & 3))) * 16 + hA * 8))
    const uint32_t oa[2][4] = {
        { STGOFF(gid,      fA), STGOFF(gid + 8,  fA), STGOFF(gid,      fA + 2), STGOFF(gid + 8,  fA + 2) },
        { STGOFF(gid + 16, fA), STGOFF(gid + 24, fA), STGOFF(gid + 16, fA + 2), STGOFF(gid + 24, fA + 2) }
    };
#undef STGOFF

    int cb = 0, ci = 2;   // consume buffer, prefetch buffer (mod-3 ring)
    for (int c = 0; c < NCH; c++) {
        if (c + 2 < NCH) {
            const uint32_t dst = stg + ci * 2048;
            const float* src = Kw + (c + 2) * CC;
#pragma unroll
            for (int i = 0; i < 4; i++) {
                int g = i * 32 + lane, r = g >> 2, f = g & 3;
                CP_ASYNC16(dst + (uint32_t)(r * 4 + (f ^ (r & 3))) * 16,
                           src + (size_t)r * DD + f * 4);
            }
            CP_COMMIT();
            CP_WAITN(2);
        } else {
            if (c + 2 == NCH) CP_WAITN(1);
            else              CP_WAITN(0);
        }

        const char* buf = smem + (stg - sb) + cb * 2048;
        uint32_t ah[2][4], al[2][4];
#pragma unroll
        for (int rr = 0; rr < 2; rr++)
#pragma unroll
            for (int i = 0; i < 4; i++)
                bfsplit(*(const float2*)(buf + oa[rr][i]), ah[rr][i], al[rr][i]);

        const int dglob = c * CC + tig * 2;
#pragma unroll
        for (int nt = 0; nt < 3; nt++) {
            int q = nt * 8 + gid; if (q > 17) q = 17;   // clamp pad rows
            const char* qh = smem + SM_QHI + q * QSTR + dglob * 2;
            const char* ql = smem + SM_QLO + q * QSTR + dglob * 2;
            uint32_t bh0 = *(const uint32_t*)qh;
            uint32_t bh1 = *(const uint32_t*)(qh + 16);
            uint32_t bl0 = *(const uint32_t*)ql;
            uint32_t bl1 = *(const uint32_t*)(ql + 16);
#pragma unroll
            for (int rr = 0; rr < 2; rr++) {
                MMA(acc[rr][nt], ah[rr][0], ah[rr][1], ah[rr][2], ah[rr][3], bh0, bh1);
                MMA(acc[rr][nt], ah[rr][0], ah[rr][1], ah[rr][2], ah[rr][3], bl0, bl1);
                MMA(acc[rr][nt], al[rr][0], al[rr][1], al[rr][2], al[rr][3], bh0, bh1);
            }
        }
        cb = (cb == 2) ? 0 : cb + 1;
        ci = (ci == 2) ? 0 : ci + 1;
    }

    // epilogue: mask + exp + fp16 transposed store + per-q row sums
    const int u8 = *(volatile int*)(smem + SM_U8);
    const unsigned char* M8  = (const unsigned char*)Mv;
    const int*           M32 = (const int*)Mv;
    float* red = (float*)(smem + SM_RED);
#pragma unroll
    for (int nt = 0; nt < 3; nt++) {
        const int q0 = nt * 8 + tig * 2, q1 = q0 + 1;
        float s0 = 0.f, s1 = 0.f;
        if (q0 < LQ) {
#pragma unroll
            for (int rr = 0; rr < 2; rr++) {
                const int ra = M0 + rr * 16 + gid, rb2 = ra + 8;
                const size_t o0 = ((size_t)b * LQ + q0) * LK + k0;
                const size_t o1 = ((size_t)b * LQ + q1) * LK + k0;
                int m0 = u8 ? (int)M8[o0 + ra]  : M32[o0 + ra];
                int m1 = u8 ? (int)M8[o1 + ra]  : M32[o1 + ra];
                int m2 = u8 ? (int)M8[o0 + rb2] : M32[o0 + rb2];
                int m3 = u8 ? (int)M8[o1 + rb2] : M32[o1 + rb2];
                float e0 = m0 ? 0.f : __expf(acc[rr][nt][0] * SCALE_F);
                float e1 = m1 ? 0.f : __expf(acc[rr][nt][1] * SCALE_F);
                float e2 = m2 ? 0.f : __expf(acc[rr][nt][2] * SCALE_F);
                float e3 = m3 ? 0.f : __expf(acc[rr][nt][3] * SCALE_F);
                *(__half2*)(g_h + ((size_t)b * LK + k0 + ra) * GH_STRIDE + q0) =
                    __floats2half2_rn(e0, e1);
                *(__half2*)(g_h + ((size_t)b * LK + k0 + rb2) * GH_STRIDE + q0) =
                    __floats2half2_rn(e2, e3);
                s0 += e0 + e2;
                s1 += e1 + e3;
            }
        }
#pragma unroll
        for (int m = 4; m <= 16; m <<= 1) {
            s0 += __shfl_xor_sync(0xffffffffu, s0, m);
            s1 += __shfl_xor_sync(0xffffffffu, s1, m);
        }
        if (gid == 0) {
            if (q0 < LQ) red[w * 24 + q0] = s0;
            if (q1 < LQ) red[w * 24 + q1] = s1;
        }
    }
    __syncthreads();
    if (tid < LQ) {
        float l = 0.f;
#pragma unroll
        for (int ww = 0; ww < 8; ww++) l += red[ww * 24 + tid];
        g_lp[b][mt][tid] = l;
    }
}

// ---------------- p2: attn_fc (fp16 rows) + context ----------------
__global__ __launch_bounds__(T2) void p2(const float* __restrict__ V,
                                         const float* __restrict__ W,
                                         float* __restrict__ out) {
    __shared__ float wl[LQ];
    __shared__ float sa[TK2];
    __shared__ int s_last;
    const int tid  = threadIdx.x;
    const int b    = blockIdx.y;
    const int tile = blockIdx.x;
    const int k0   = tile * TK2;

    if (tid < LQ) {
        float l = 0.f;
#pragma unroll
        for (int t = 0; t < NMT; t++) l += g_lp[b][t][tid];
        wl[tid] = W[tid] / l;
    }
    __syncthreads();

    for (int kk = tid; kk < TK2; kk += T2) {
        const int k = k0 + kk;
        const char* rp = (const char*)(g_h + ((size_t)b * LK + k) * GH_STRIDE);
        uint4 u0 = *(const uint4*)rp;            // q 0..7
        uint4 u1 = *(const uint4*)(rp + 16);     // q 8..15
        uint32_t u2 = *(const uint32_t*)(rp + 32); // q 16..17
        uint32_t uu[9] = {u0.x, u0.y, u0.z, u0.w, u1.x, u1.y, u1.z, u1.w, u2};
        float a = 0.f;
#pragma unroll
        for (int j = 0; j < 9; j++) {
            float2 f = __half22float2(*reinterpret_cast<__half2*>(&uu[j]));
            a = fmaf(f.x, wl[2*j],     a);
            a = fmaf(f.y, wl[2*j + 1], a);
        }
        out[(size_t)NB*DD + (size_t)b*LK + k] = a;
        sa[kk] = a;
    }
    __syncthreads();

    const float4* V4 = (const float4*)(V + ((size_t)b*LK + k0)*DD);
    float cx = 0.f, cy = 0.f, cz = 0.f, cw = 0.f;
#pragma unroll 8
    for (int kk = 0; kk < TK2; kk++) {
        float  av = sa[kk];
        float4 v  = V4[(size_t)kk*(DD/4) + tid];
        cx = fmaf(av, v.x, cx);
        cy = fmaf(av, v.y, cy);
        cz = fmaf(av, v.z, cz);
        cw = fmaf(av, v.w, cw);
    }
    ((float4*)g_cp[b][tile])[tid] = make_float4(cx, cy, cz, cw);
    __threadfence();
    __syncthreads();
    if (tid == 0) s_last = (atomicAdd(&g_cnt[b], 1) == NT2 - 1);
    __syncthreads();
    if (s_last) {
        float4 a = make_float4(0.f, 0.f, 0.f, 0.f);
#pragma unroll
        for (int t = 0; t < NT2; t++) {
            float4 v = ((const float4*)g_cp[b][t])[tid];
            a.x += v.x; a.y += v.y; a.z += v.z; a.w += v.w;
        }
        ((float4*)(out + (size_t)b*DD))[tid] = a;
        if (tid == 0) g_cnt[b] = 0;
    }
}

extern "C" void kernel_launch(void* const* d_in, const int* in_sizes, int n_in,
                              void* d_out, int out_size) {
    const float* Q = (const float*)d_in[0];
    const float* K = (const float*)d_in[1];
    const float* V = (const float*)d_in[2];
    const void*  M = d_in[3];
    const float* W = (const float*)d_in[4];
    float* out = (float*)d_out;

    cudaFuncSetAttribute(p1, cudaFuncAttributeMaxDynamicSharedMemorySize, SMEM1_BYTES);

    p1<<<dim3(NMT, NB), T1, SMEM1_BYTES>>>(Q, K, M);
    p2<<<dim3(NT2, NB), T2>>>(V, W, out);
}

// round 13
// speedup vs baseline: 1.1173x; 1.0002x over previous
#include <cuda_runtime.h>
#include <cuda_fp16.h>
#include <cstdint>

#define NB 32
#define LQ 18
#define LK 4096
#define DD 768
#define SCALE_F 0.03608439182435161f   // 1/sqrt(768)

// ---- p1 config ----
#define T1   256
#define MT   256             // k-rows per p1 block (2 MMA row-blocks per warp)
#define NMT  (LK/MT)         // 16
#define CC   16              // K cols per chunk
#define NCH  (DD/CC)         // 48
#define QSTR 1544            // Q row stride bytes (768*2 + 8 pad)
#define WSTG 6144            // per-warp staging: 3 bufs x 2048B (32 rows x 64B)

// smem layout (bytes)
#define SM_U8   0
#define SM_RED  192          // 8 warps * 24 floats = 768B -> ends 960
#define SM_QHI  1024         // 27792
#define SM_QLO  28816        // 27792 -> ends 56608
#define SM_STG  56640        // 8 warps * 6144
#define SMEM1_BYTES (SM_STG + 8*WSTG)   // 105792

// scratch row: 24 halves (48B) per (b,k); q 18..23 = pad (never written, zero-init)
#define GH_STRIDE 24

// ---- p2 config ----
#define TK2 256
#define NT2 (LK/TK2)         // 16
#define T2  192

// ---- device scratch ----
__device__ __half g_h[(size_t)NB*LK*GH_STRIDE];   // exp(scores) fp16, transposed
__device__ float  g_lp[NB][NMT][LQ];
__device__ float  g_cp[NB][NT2][DD];
__device__ int    g_cnt[NB];

__device__ __forceinline__ uint32_t bfpack(float a, float b) {   // low16=bf16(a)
    uint32_t r;
    asm("cvt.rn.bf16x2.f32 %0, %1, %2;" : "=r"(r) : "f"(b), "f"(a));
    return r;
}
__device__ __forceinline__ float bflo_f(uint32_t h) { return __uint_as_float(h << 16); }
__device__ __forceinline__ float bfhi_f(uint32_t h) { return __uint_as_float(h & 0xffff0000u); }
__device__ __forceinline__ uint32_t smem_u32(const void* p) {
    uint32_t a;
    asm("{ .reg .u64 t; cvta.to.shared.u64 t, %1; cvt.u32.u64 %0, t; }" : "=r"(a) : "l"(p));
    return a;
}
#define CP_ASYNC16(dst, src) \
    asm volatile("cp.async.cg.shared.global [%0], [%1], 16;" :: "r"(dst), "l"(src) : "memory")
#define CP_COMMIT() asm volatile("cp.async.commit_group;" ::: "memory")
#define CP_WAITN(n) asm volatile("cp.async.wait_group %0;" :: "n"(n) : "memory")
#define MMA(ac, a0,a1,a2,a3, b0,b1) \
    asm volatile("mma.sync.aligned.m16n8k16.row.col.f32.bf16.bf16.f32 " \
        "{%0,%1,%2,%3}, {%4,%5,%6,%7}, {%8,%9}, {%0,%1,%2,%3};" \
        : "+f"((ac)[0]),"+f"((ac)[1]),"+f"((ac)[2]),"+f"((ac)[3]) \
        : "r"(a0),"r"(a1),"r"(a2),"r"(a3),"r"(b0),"r"(b1))

__device__ __forceinline__ void bfsplit(float2 v, uint32_t& h, uint32_t& l) {
    h = bfpack(v.x, v.y);
    l = bfpack(v.x - bflo_f(h), v.y - bfhi_f(h));
}

// ---------------- p1: 256-row tiles, register-fragment split-bf16 mma.sync ----------------
__global__ __launch_bounds__(T1, 2) void p1(const float* __restrict__ Q,
                                            const float* __restrict__ K,
                                            const void* __restrict__ Mv) {
    extern __shared__ char smem[];
    const uint32_t sb = smem_u32(smem);
    const int tid = threadIdx.x, w = tid >> 5, lane = tid & 31;
    const int gid = lane >> 2, tig = lane & 3;
    const int b = blockIdx.y, mt = blockIdx.x, k0 = mt * MT;
    const int M0 = w * 32;                 // warp owns 32 k-rows

    if (tid == 0) *(int*)(smem + SM_U8) = 0;
    __syncthreads();
    // mask dtype probe: int32 0/1 has zero bytes at offsets %4!=0; u8 bool does not
    if (tid < 64) {
        uchar4 v = ((const uchar4*)Mv)[tid];
        if (v.y | v.z | v.w) atomicOr((int*)(smem + SM_U8), 1);
    }

    // per-warp staging: chunk = 32 rows x 16 f32 (64B/row), xor-swizzled float4s
    const uint32_t stg = sb + SM_STG + w * WSTG;
    const float* Kw = K + ((size_t)b * LK + k0 + M0) * DD;

    // issue chunks 0,1 (depth-3 ring: bufs 0,1,2)
#pragma unroll
    for (int cc = 0; cc < 2; cc++) {
        const uint32_t dst = stg + cc * 2048;
        const float* src = Kw + cc * CC;
#pragma unroll
        for (int i = 0; i < 4; i++) {
            int g = i * 32 + lane, r = g >> 2, f = g & 3;
            CP_ASYNC16(dst + (uint32_t)(r * 4 + (f ^ (r & 3))) * 16,
                       src + (size_t)r * DD + f * 4);
        }
        CP_COMMIT();
    }

    {   // Q -> bf16 hi/lo smem (once per block)
        const float4* Q4 = (const float4*)(Q + (size_t)b * LQ * DD);
        for (int idx = tid; idx < LQ * 192; idx += T1) {
            int q = idx / 192, f = idx % 192;
            float4 v = Q4[idx];
            uint32_t h0 = bfpack(v.x, v.y), h1 = bfpack(v.z, v.w);
            uint32_t l0 = bfpack(v.x - bflo_f(h0), v.y - bfhi_f(h0));
            uint32_t l1 = bfpack(v.z - bflo_f(h1), v.w - bfhi_f(h1));
            *(uint2*)(smem + SM_QHI + q * QSTR + f * 8) = make_uint2(h0, h1);
            *(uint2*)(smem + SM_QLO + q * QSTR + f * 8) = make_uint2(l0, l1);
        }
    }
    __syncthreads();   // Q visible; u8 flag final; main loop sync-free

    // ---- mask register-prefetch: 24 loads issued NOW, latency hidden by MMA loop ----
    const int u8 = *(volatile int*)(smem + SM_U8);
    const unsigned char* M8  = (const unsigned char*)Mv;
    const int*           M32 = (const int*)Mv;
    uint32_t mbits = 0;    // bit (nt*8 + rr*4 + j) = mask for (q0+j%2, row ra/rb2)
#pragma unroll
    for (int nt = 0; nt < 3; nt++) {
        const int q0 = nt * 8 + tig * 2, q1 = q0 + 1;
        if (q0 < LQ) {
#pragma unroll
            for (int rr = 0; rr < 2; rr++) {
                const int ra = M0 + rr * 16 + gid, rb2 = ra + 8;
                const size_t o0 = ((size_t)b * LQ + q0) * LK + k0;
                const size_t o1 = ((size_t)b * LQ + q1) * LK + k0;
                int m0, m1, m2, m3;
                if (u8) {
                    m0 = __ldcs(M8 + o0 + ra);  m1 = __ldcs(M8 + o1 + ra);
                    m2 = __ldcs(M8 + o0 + rb2); m3 = __ldcs(M8 + o1 + rb2);
                } else {
                    m0 = __ldcs(M32 + o0 + ra);  m1 = __ldcs(M32 + o1 + ra);
                    m2 = __ldcs(M32 + o0 + rb2); m3 = __ldcs(M32 + o1 + rb2);
                }
                const int sh = nt * 8 + rr * 4;
                mbits |= ((m0 ? 1u : 0u) | (m1 ? 2u : 0u) | (m2 ? 4u : 0u) | (m3 ? 8u : 0u)) << sh;
            }
        }
    }

    float acc[2][3][4];
#pragma unroll
    for (int rr = 0; rr < 2; rr++)
#pragma unroll
        for (int nt = 0; nt < 3; nt++)
#pragma unroll
            for (int i = 0; i < 4; i++) acc[rr][nt][i] = 0.f;

    // fragment offsets (local rows within warp's 32-row staging)
    const int fA = tig >> 1, hA = tig & 1;
#define STGOFF(r, f) ((uint32_t)(((r) * 4 + ((f) ^ ((r) & 3))) * 16 + hA * 8))
    const uint32_t oa[2][4] = {
        { STGOFF(gid,      fA), STGOFF(gid + 8,  fA), STGOFF(gid,      fA + 2), STGOFF(gid + 8,  fA + 2) },
        { STGOFF(gid + 16, fA), STGOFF(gid + 24, fA), STGOFF(gid + 16, fA + 2), STGOFF(gid + 24, fA + 2) }
    };
#undef STGOFF

    int cb = 0, ci = 2;   // consume buffer, prefetch buffer (mod-3 ring)
    for (int c = 0; c < NCH; c++) {
        if (c + 2 < NCH) {
            const uint32_t dst = stg + ci * 2048;
            const float* src = Kw + (c + 2) * CC;
#pragma unroll
            for (int i = 0; i < 4; i++) {
                int g = i * 32 + lane, r = g >> 2, f = g & 3;
                CP_ASYNC16(dst + (uint32_t)(r * 4 + (f ^ (r & 3))) * 16,
                           src + (size_t)r * DD + f * 4);
            }
            CP_COMMIT();
            CP_WAITN(2);
        } else {
            if (c + 2 == NCH) CP_WAITN(1);
            else              CP_WAITN(0);
        }

        const char* buf = smem + (stg - sb) + cb * 2048;
        uint32_t ah[2][4], al[2][4];
#pragma unroll
        for (int rr = 0; rr < 2; rr++)
#pragma unroll
            for (int i = 0; i < 4; i++)
                bfsplit(*(const float2*)(buf + oa[rr][i]), ah[rr][i], al[rr][i]);

        const int dglob = c * CC + tig * 2;
#pragma unroll
        for (int nt = 0; nt < 3; nt++) {
            int q = nt * 8 + gid; if (q > 17) q = 17;   // clamp pad rows
            const char* qh = smem + SM_QHI + q * QSTR + dglob * 2;
            const char* ql = smem + SM_QLO + q * QSTR + dglob * 2;
            uint32_t bh0 = *(const uint32_t*)qh;
            uint32_t bh1 = *(const uint32_t*)(qh + 16);
            uint32_t bl0 = *(const uint32_t*)ql;
            uint32_t bl1 = *(const uint32_t*)(ql + 16);
#pragma unroll
            for (int rr = 0; rr < 2; rr++) {
                MMA(acc[rr][nt], ah[rr][0], ah[rr][1], ah[rr][2], ah[rr][3], bh0, bh1);
                MMA(acc[rr][nt], ah[rr][0], ah[rr][1], ah[rr][2], ah[rr][3], bl0, bl1);
                MMA(acc[rr][nt], al[rr][0], al[rr][1], al[rr][2], al[rr][3], bh0, bh1);
            }
        }
        cb = (cb == 2) ? 0 : cb + 1;
        ci = (ci == 2) ? 0 : ci + 1;
    }

    // epilogue: masked exp + fp16 transposed store + per-q row sums (mask already in mbits)
    float* red = (float*)(smem + SM_RED);
#pragma unroll
    for (int nt = 0; nt < 3; nt++) {
        const int q0 = nt * 8 + tig * 2, q1 = q0 + 1;
        float s0 = 0.f, s1 = 0.f;
        if (q0 < LQ) {
#pragma unroll
            for (int rr = 0; rr < 2; rr++) {
                const int ra = M0 + rr * 16 + gid, rb2 = ra + 8;
                const uint32_t mb = mbits >> (nt * 8 + rr * 4);
                float e0 = (mb & 1u) ? 0.f : __expf(acc[rr][nt][0] * SCALE_F);
                float e1 = (mb & 2u) ? 0.f : __expf(acc[rr][nt][1] * SCALE_F);
                float e2 = (mb & 4u) ? 0.f : __expf(acc[rr][nt][2] * SCALE_F);
                float e3 = (mb & 8u) ? 0.f : __expf(acc[rr][nt][3] * SCALE_F);
                *(__half2*)(g_h + ((size_t)b * LK + k0 + ra) * GH_STRIDE + q0) =
                    __floats2half2_rn(e0, e1);
                *(__half2*)(g_h + ((size_t)b * LK + k0 + rb2) * GH_STRIDE + q0) =
                    __floats2half2_rn(e2, e3);
                s0 += e0 + e2;
                s1 += e1 + e3;
            }
        }
#pragma unroll
        for (int m = 4; m <= 16; m <<= 1) {
            s0 += __shfl_xor_sync(0xffffffffu, s0, m);
            s1 += __shfl_xor_sync(0xffffffffu, s1, m);
        }
        if (gid == 0) {
            if (q0 < LQ) red[w * 24 + q0] = s0;
            if (q1 < LQ) red[w * 24 + q1] = s1;
        }
    }
    __syncthreads();
    if (tid < LQ) {
        float l = 0.f;
#pragma unroll
        for (int ww = 0; ww < 8; ww++) l += red[ww * 24 + tid];
        g_lp[b][mt][tid] = l;
    }
}

// ---------------- p2: attn_fc (fp16 rows) + context ----------------
__global__ __launch_bounds__(T2) void p2(const float* __restrict__ V,
                                         const float* __restrict__ W,
                                         float* __restrict__ out) {
    __shared__ float wl[LQ];
    __shared__ float sa[TK2];
    __shared__ int s_last;
    const int tid  = threadIdx.x;
    const int b    = blockIdx.y;
    const int tile = blockIdx.x;
    const int k0   = tile * TK2;

    if (tid < LQ) {
        float l = 0.f;
#pragma unroll
        for (int t = 0; t < NMT; t++) l += g_lp[b][t][tid];
        wl[tid] = W[tid] / l;
    }
    __syncthreads();

    for (int kk = tid; kk < TK2; kk += T2) {
        const int k = k0 + kk;
        const char* rp = (const char*)(g_h + ((size_t)b * LK + k) * GH_STRIDE);
        uint4 u0 = *(const uint4*)rp;              // q 0..7
        uint4 u1 = *(const uint4*)(rp + 16);       // q 8..15
        uint32_t u2 = *(const uint32_t*)(rp + 32); // q 16..17
        uint32_t uu[9] = {u0.x, u0.y, u0.z, u0.w, u1.x, u1.y, u1.z, u1.w, u2};
        float a = 0.f;
#pragma unroll
        for (int j = 0; j < 9; j++) {
            float2 f = __half22float2(*reinterpret_cast<__half2*>(&uu[j]));
            a = fmaf(f.x, wl[2*j],     a);
            a = fmaf(f.y, wl[2*j + 1], a);
        }
        out[(size_t)NB*DD + (size_t)b*LK + k] = a;
        sa[kk] = a;
    }
    __syncthreads();

    const float4* V4 = (const float4*)(V + ((size_t)b*LK + k0)*DD);
    float cx = 0.f, cy = 0.f, cz = 0.f, cw = 0.f;
#pragma unroll 8
    for (int kk = 0; kk < TK2; kk++) {
        float  av = sa[kk];
        float4 v  = __ldcs(V4 + (size_t)kk*(DD/4) + tid);   // evict-first: protect g_h in L2
        cx = fmaf(av, v.x, cx);
        cy = fmaf(av, v.y, cy);
        cz = fmaf(av, v.z, cz);
        cw = fmaf(av, v.w, cw);
    }
    ((float4*)g_cp[b][tile])[tid] = make_float4(cx, cy, cz, cw);
    __threadfence();
    __syncthreads();
    if (tid == 0) s_last = (atomicAdd(&g_cnt[b], 1) == NT2 - 1);
    __syncthreads();
    if (s_last) {
        float4 a = make_float4(0.f, 0.f, 0.f, 0.f);
#pragma unroll
        for (int t = 0; t < NT2; t++) {
            float4 v = ((const float4*)g_cp[b][t])[tid];
            a.x += v.x; a.y += v.y; a.z += v.z; a.w += v.w;
        }
        ((float4*)(out + (size_t)b*DD))[tid] = a;
        if (tid == 0) g_cnt[b] = 0;
    }
}

extern "C" void kernel_launch(void* const* d_in, const int* in_sizes, int n_in,
                              void* d_out, int out_size) {
    const float* Q = (const float*)d_in[0];
    const float* K = (const float*)d_in[1];
    const float* V = (const float*)d_in[2];
    const void*  M = d_in[3];
    const float* W = (const float*)d_in[4];
    float* out = (float*)d_out;

    cudaFuncSetAttribute(p1, cudaFuncAttributeMaxDynamicSharedMemorySize, SMEM1_BYTES);

    p1<<<dim3(NMT, NB), T1, SMEM1_BYTES>>>(Q, K, M);
    p2<<<dim3(NT2, NB), T2>>>(V, W, out);
}